// round 17
// baseline (speedup 1.0000x reference)
#include <cuda_runtime.h>
#include <cuda_fp16.h>
#include <cstdint>
#include <math.h>

#define NT 512
#define NH 2048
#define NE 60
#define NI 1408
#define NS 5632
#define KTOP 4
#define NPAIR (NT*KTOP)

// ---------------- device scratch (static, no allocations) ----------------
__device__ __align__(16) __half g_Ab[NPAIR * NI];   // routed act, fp16
__device__ __align__(16) __half g_Bs[NT * NS];      // shared act, fp16
__device__ __align__(16) __half g_xh[NT * NH];      // hidden states, fp16
__device__ int   g_pair_tok[NPAIR];
__device__ float g_pair_w[NPAIR];
__device__ int   g_cnt[NE];
__device__ int   g_off[NE + 1];
__device__ int   g_cur[NE];
__device__ float g_sg[NT];
__device__ int   g_tok_e[NT * KTOP];
__device__ float g_tok_w[NT * KTOP];

// ---------------- helpers ----------------
__device__ __forceinline__ uint32_t s2u(const void* p) { return (uint32_t)__cvta_generic_to_shared(p); }
__device__ __forceinline__ void cpa16(uint32_t s, const void* g) {
    asm volatile("cp.async.cg.shared.global [%0], [%1], 16;" :: "r"(s), "l"(g));
}
__device__ __forceinline__ void cpcommit() { asm volatile("cp.async.commit_group;"); }
__device__ __forceinline__ void cpwait1()  { asm volatile("cp.async.wait_group 1;"); }
__device__ __forceinline__ float silu_mul(float h1, float h3) { return h3 * (h1 / (1.0f + expf(-h1))); }
__device__ __forceinline__ uint32_t pack_h2(float lo, float hi) {
    __half2 h = __floats2half2_rn(lo, hi);
    return *reinterpret_cast<uint32_t*>(&h);
}
__device__ __forceinline__ void mma16(float* c, const uint32_t* a, uint32_t b0, uint32_t b1) {
    asm volatile(
        "mma.sync.aligned.m16n8k16.row.col.f32.f16.f16.f32 "
        "{%0,%1,%2,%3}, {%4,%5,%6,%7}, {%8,%9}, {%0,%1,%2,%3};"
        : "+f"(c[0]), "+f"(c[1]), "+f"(c[2]), "+f"(c[3])
        : "r"(a[0]), "r"(a[1]), "r"(a[2]), "r"(a[3]), "r"(b0), "r"(b1));
}
__device__ __forceinline__ void ldm4(uint32_t* a, uint32_t addr) {
    asm volatile("ldmatrix.sync.aligned.m8n8.x4.shared.b16 {%0,%1,%2,%3}, [%4];"
                 : "=r"(a[0]), "=r"(a[1]), "=r"(a[2]), "=r"(a[3]) : "r"(addr));
}
__device__ __forceinline__ void ldm4t(uint32_t* a, uint32_t addr) {
    asm volatile("ldmatrix.sync.aligned.m8n8.x4.trans.shared.b16 {%0,%1,%2,%3}, [%4];"
                 : "=r"(a[0]), "=r"(a[1]), "=r"(a[2]), "=r"(a[3]) : "r"(addr));
}

// ---------------- pre: x -> fp16, and reset routing counters ----------------
__global__ __launch_bounds__(256) void k_pre(const float* __restrict__ x) {
    if (blockIdx.x == 0 && threadIdx.x < NE) { g_cnt[threadIdx.x] = 0; g_cur[threadIdx.x] = 0; }
    int i = blockIdx.x * 256 + threadIdx.x;          // NT*NH/4 threads
    float4 v = reinterpret_cast<const float4*>(x)[i];
    uint2 o; o.x = pack_h2(v.x, v.y); o.y = pack_h2(v.z, v.w);
    reinterpret_cast<uint2*>(g_xh)[i] = o;
}

// ---------------- router ----------------
__global__ __launch_bounds__(256) void k_router(const float* __restrict__ x,
                                                const float* __restrict__ gw,
                                                const float* __restrict__ sgw) {
    __shared__ __align__(16) float xs[4][NH];
    __shared__ float lg[4][64];
    const int t0 = blockIdx.x * 4, tid = threadIdx.x;
    const float4* xg = reinterpret_cast<const float4*>(x + (size_t)t0 * NH);
    float4* xv = reinterpret_cast<float4*>(&xs[0][0]);
    for (int i = tid; i < 4 * NH / 4; i += 256) xv[i] = xg[i];
    __syncthreads();
    if (tid < 4 * 61) {
        const int tl = tid / 61, e = tid % 61;
        float acc = 0.f;
        if (e < NE) {
            #pragma unroll 8
            for (int h = 0; h < NH; h++) acc += xs[tl][h] * gw[h * NE + e];
            lg[tl][e] = acc;
        } else {
            #pragma unroll 8
            for (int h = 0; h < NH; h++) acc += xs[tl][h] * sgw[h];
            g_sg[t0 + tl] = 1.f / (1.f + expf(-acc));
        }
    }
    __syncthreads();
    if (tid < 4) {
        float mx = -1e30f;
        for (int e = 0; e < NE; e++) mx = fmaxf(mx, lg[tid][e]);
        float s = 0.f;
        for (int e = 0; e < NE; e++) { float p = expf(lg[tid][e] - mx); lg[tid][e] = p; s += p; }
        const float inv = 1.f / s;
        for (int k = 0; k < KTOP; k++) {
            float best = -1.f; int bi = 0;
            for (int e = 0; e < NE; e++) { float v = lg[tid][e]; if (v > best) { best = v; bi = e; } }
            lg[tid][bi] = -2.f;
            g_tok_e[(t0 + tid) * KTOP + k] = bi;
            g_tok_w[(t0 + tid) * KTOP + k] = best * inv;
            atomicAdd(&g_cnt[bi], 1);
        }
    }
}

// ---------------- fused scan + scatter (1 block) ----------------
__global__ __launch_bounds__(512) void k_scansc() {
    if (threadIdx.x == 0) {
        int o = 0;
        for (int e = 0; e < NE; e++) { g_off[e] = o; o += g_cnt[e]; }
        g_off[NE] = o;
    }
    __syncthreads();
    const int t = threadIdx.x;
    if (t < NT) {
        for (int k = 0; k < KTOP; k++) {
            const int e = g_tok_e[t * KTOP + k];
            const int p = g_off[e] + atomicAdd(&g_cur[e], 1);
            g_pair_tok[p] = t;
            g_pair_w[p] = g_tok_w[t * KTOP + k];
        }
    }
}

// ================= unified fp16 mma.sync GEMM =================
// Block BM x 128, warp tile 32x32, BK=32, STAGES-deep cp.async ring.
// A: fp16 activations via ldmatrix.x4.
// B: fp32 weights staged via cp.async, converted once per stage to a shared
//    fp16 buffer, fragments fetched via ldmatrix.x4.trans.
// EPI: 0 = silu(D1)*D3 -> half act buffer (dual B); 1 = sigmoid-scaled store;
//      2 = pair_w-weighted atomicAdd.
template<int EPI, int ROUTED, int BM, int KD, int BSTR, int STAGES, int MINB>
__global__ void __launch_bounds__(BM * 4, MINB) k_g(const float* __restrict__ B1p,
                                                    const float* __restrict__ B3p,
                                                    float* __restrict__ O) {
    constexpr int DUAL = (EPI == 0) ? 1 : 0;
    constexpr int THREADS = BM * 4;
    constexpr int ABYTES = BM * 80;                   // 32 half (64B) + 16B pad per row
    constexpr int STG = ABYTES + 16896 * (1 + DUAL);  // fp32 B: 32 rows x 528B each matrix
    constexpr int BHOFF = STAGES * STG;               // fp16 B buffer (single, reused)
    constexpr int BHMAT = 32 * 272;                   // 8704 B per matrix (pitch 272B)
    extern __shared__ __align__(16) char smem[];
    const int tid = threadIdx.x;
    const int n0 = blockIdx.x * 128;
    int seg0 = 0, ne = 1 << 30, m0;
    if (ROUTED) {
        const int e = blockIdx.y;
        seg0 = g_off[e]; ne = g_off[e + 1] - seg0;
        m0 = blockIdx.z * BM;
        if (m0 >= ne) return;
        B1p += (size_t)e * KD * BSTR;
        if (DUAL) B3p += (size_t)e * KD * BSTR;
    } else m0 = blockIdx.y * BM;

    // A source row (half)
    const int arow_l = tid >> 2, achk = tid & 3;
    int arow = m0 + arow_l;
    if (ROUTED && arow >= ne) arow = ne - 1;
    const __half* aptr;
    if (EPI == 0)      aptr = g_xh + (size_t)(ROUTED ? g_pair_tok[seg0 + arow] : arow) * NH;
    else if (EPI == 1) aptr = g_Bs + (size_t)arow * NS;
    else               aptr = g_Ab + (size_t)(seg0 + arow) * NI;
    aptr += achk * 8;

    const uint32_t sb = s2u(smem);
    const uint32_t adst = sb + arow_l * 80 + achk * 16;

    auto load_stage = [&](int s, int kk) {
        const int k0 = kk * 32;
        cpa16(adst + s * STG, aptr + k0);
        constexpr int NB = 1024 * (1 + DUAL) / THREADS;
        #pragma unroll
        for (int it = 0; it < NB; it++) {
            const int idx = tid + it * THREADS;
            const int mat = idx >> 10, row = (idx >> 5) & 31, chk = idx & 31;
            const float* src = ((DUAL && mat) ? B3p : B1p) + (size_t)(k0 + row) * BSTR + n0 + chk * 4;
            cpa16(sb + s * STG + ABYTES + mat * 16896 + row * 528 + chk * 16, src);
        }
    };
    load_stage(0, 0); cpcommit();
    load_stage(1, 1); cpcommit();

    const int lane = tid & 31, w = tid >> 5;
    const int g = lane >> 2, tg = lane & 3;
    const int wm = (w >> 2) * 32, wn = (w & 3) * 32;
    // A ldmatrix lane base (pitch 80B)
    const int lmr = lane & 7, lmg = lane >> 3;
    const uint32_t a_lm_base = sb + (uint32_t)(wm + (lmg & 1) * 8 + lmr) * 80 + (uint32_t)(lmg >> 1) * 16;
    // B ldmatrix.trans lane base (fp16 buffer, pitch 272B)
    // tiles: 0=(kL,nA) 1=(kU,nA) 2=(kL,nB) 3=(kU,nB); per (mat,h,p): + mat*BHMAT + h*4352 + p*32
    const int btile = lane >> 3, btr = lane & 7;
    const uint32_t b_lm_base = sb + BHOFF + (uint32_t)((btile & 1) * 8 + btr) * 272
                                         + (uint32_t)(wn + (btile >> 1) * 8) * 2;

    float c1[2][4][4], c3[2][4][4];
    #pragma unroll
    for (int im = 0; im < 2; im++)
        #pragma unroll
        for (int in = 0; in < 4; in++)
            #pragma unroll
            for (int q = 0; q < 4; q++) { c1[im][in][q] = 0.f; c3[im][in][q] = 0.f; }

    const int NK = KD / 32;
    for (int kk = 0; kk < NK; kk++) {
        const int s = kk % STAGES;
        cpwait1();
        __syncthreads();                       // stage data ready; prior Bh readers done
        // convert fp32 B stage -> fp16 buffer
        {
            constexpr int NCH = (1 + DUAL) * 1024 / THREADS;   // float4 chunks per thread
            #pragma unroll
            for (int c = 0; c < NCH; c++) {
                const int idx = tid + c * THREADS;
                const int mat = idx >> 10, r = (idx >> 5) & 31, q = idx & 31;
                float4 v = *reinterpret_cast<const float4*>(
                    smem + s * STG + ABYTES + mat * 16896 + r * 528 + q * 16);
                uint2 o; o.x = pack_h2(v.x, v.y); o.y = pack_h2(v.z, v.w);
                *reinterpret_cast<uint2*>(smem + BHOFF + mat * BHMAT + r * 272 + q * 8) = o;
            }
        }
        __syncthreads();                       // fp16 buffer visible to all warps
        #pragma unroll
        for (int h = 0; h < 2; h++) {
            uint32_t a[2][4];
            ldm4(a[0], a_lm_base + s * STG + h * 32);
            ldm4(a[1], a_lm_base + s * STG + 16 * 80 + h * 32);
            #pragma unroll
            for (int p = 0; p < 2; p++) {
                uint32_t b[4];
                ldm4t(b, b_lm_base + h * 4352 + p * 32);
                mma16(c1[0][2 * p],     a[0], b[0], b[1]);
                mma16(c1[1][2 * p],     a[1], b[0], b[1]);
                mma16(c1[0][2 * p + 1], a[0], b[2], b[3]);
                mma16(c1[1][2 * p + 1], a[1], b[2], b[3]);
                if (DUAL) {
                    uint32_t d[4];
                    ldm4t(d, b_lm_base + BHMAT + h * 4352 + p * 32);
                    mma16(c3[0][2 * p],     a[0], d[0], d[1]);
                    mma16(c3[1][2 * p],     a[1], d[0], d[1]);
                    mma16(c3[0][2 * p + 1], a[0], d[2], d[3]);
                    mma16(c3[1][2 * p + 1], a[1], d[2], d[3]);
                }
            }
        }
        if (STAGES == 2) __syncthreads();   // buffer kk+2 aliases kk: all readers must finish
        if (kk + 2 < NK) load_stage((kk + 2) % STAGES, kk + 2);
        cpcommit();
    }

    // ---------------- epilogue ----------------
    #pragma unroll
    for (int im = 0; im < 2; im++) {
        const int mr0 = m0 + wm + im * 16 + g, mr1 = mr0 + 8;
        if (EPI == 1) {
            const float s0 = g_sg[mr0], s1 = g_sg[mr1];
            #pragma unroll
            for (int in = 0; in < 4; in++) {
                const int col = n0 + wn + in * 8 + tg * 2;
                *reinterpret_cast<float2*>(&O[(size_t)mr0 * NH + col]) =
                    make_float2(s0 * c1[im][in][0], s0 * c1[im][in][1]);
                *reinterpret_cast<float2*>(&O[(size_t)mr1 * NH + col]) =
                    make_float2(s1 * c1[im][in][2], s1 * c1[im][in][3]);
            }
        } else if (EPI == 0) {
            #pragma unroll
            for (int in = 0; in < 4; in++) {
                const int col = n0 + wn + in * 8 + tg * 2;
                if (!ROUTED || mr0 < ne) {
                    uint32_t v = pack_h2(silu_mul(c1[im][in][0], c3[im][in][0]),
                                         silu_mul(c1[im][in][1], c3[im][in][1]));
                    __half* dst = ROUTED ? (g_Ab + (size_t)(seg0 + mr0) * NI + col)
                                         : (g_Bs + (size_t)mr0 * NS + col);
                    *reinterpret_cast<uint32_t*>(dst) = v;
                }
                if (!ROUTED || mr1 < ne) {
                    uint32_t v = pack_h2(silu_mul(c1[im][in][2], c3[im][in][2]),
                                         silu_mul(c1[im][in][3], c3[im][in][3]));
                    __half* dst = ROUTED ? (g_Ab + (size_t)(seg0 + mr1) * NI + col)
                                         : (g_Bs + (size_t)mr1 * NS + col);
                    *reinterpret_cast<uint32_t*>(dst) = v;
                }
            }
        } else {
            if (mr0 < ne) {
                const int p = seg0 + mr0; const float wv = g_pair_w[p];
                float* orow = O + (size_t)g_pair_tok[p] * NH;
                #pragma unroll
                for (int in = 0; in < 4; in++) {
                    const int col = n0 + wn + in * 8 + tg * 2;
                    atomicAdd(orow + col,     wv * c1[im][in][0]);
                    atomicAdd(orow + col + 1, wv * c1[im][in][1]);
                }
            }
            if (mr1 < ne) {
                const int p = seg0 + mr1; const float wv = g_pair_w[p];
                float* orow = O + (size_t)g_pair_tok[p] * NH;
                #pragma unroll
                for (int in = 0; in < 4; in++) {
                    const int col = n0 + wn + in * 8 + tg * 2;
                    atomicAdd(orow + col,     wv * c1[im][in][2]);
                    atomicAdd(orow + col + 1, wv * c1[im][in][3]);
                }
            }
        }
    }
}

// ---------------- launch ----------------
extern "C" void kernel_launch(void* const* d_in, const int* in_sizes, int n_in,
                              void* d_out, int out_size) {
    const float* x   = (const float*)d_in[0];
    const float* gw  = (const float*)d_in[1];
    const float* w1  = (const float*)d_in[2];
    const float* w3  = (const float*)d_in[3];
    const float* w2  = (const float*)d_in[4];
    const float* sw1 = (const float*)d_in[5];
    const float* sw3 = (const float*)d_in[6];
    const float* sw2 = (const float*)d_in[7];
    const float* sgw = (const float*)d_in[8];
    float* out = (float*)d_out;

    const int SM_SU = 3 * (128 * 80 + 2 * 16896) + 2 * 8704;  // 149504  shared_up: 3 st, 1 blk
    const int SM_MU = 2 * (64 * 80 + 2 * 16896) + 2 * 8704;   // 95232   moe_up:    2 st, 2 blk
    const int SM_DN = 3 * (64 * 80 + 16896) + 8704;           // 74752   down:      3 st, 2 blk
    cudaFuncSetAttribute(k_g<0,0,128,NH,NS,3,1>, cudaFuncAttributeMaxDynamicSharedMemorySize, SM_SU);
    cudaFuncSetAttribute(k_g<0,1,64,NH,NI,2,2>,  cudaFuncAttributeMaxDynamicSharedMemorySize, SM_MU);
    cudaFuncSetAttribute(k_g<1,0,64,NS,NH,3,2>,  cudaFuncAttributeMaxDynamicSharedMemorySize, SM_DN);
    cudaFuncSetAttribute(k_g<2,1,64,NI,NH,3,2>,  cudaFuncAttributeMaxDynamicSharedMemorySize, SM_DN);

    // order chosen so the profiler's sampled launch (#4) is k_moe_up
    k_pre<<<NT * NH / 4 / 256, 256>>>(x);
    k_router<<<NT / 4, 256>>>(x, gw, sgw);
    k_scansc<<<1, 512>>>();
    // routed up: g_Ab = silu(gather(xh)@w1e)*(gather(xh)@w3e)
    k_g<0,1,64,NH,NI,2,2><<<dim3(NI/128, NE, 8), 256, SM_MU>>>(w1, w3, nullptr);
    // shared up: g_Bs = silu(xh@sw1)*(xh@sw3)
    k_g<0,0,128,NH,NS,3,1><<<dim3(NS/128, NT/128), 512, SM_SU>>>(sw1, sw3, nullptr);
    // shared down: out = sg * (g_Bs @ sw2)   (writes every element)
    k_g<1,0,64,NS,NH,3,2><<<dim3(NH/128, NT/64), 256, SM_DN>>>(sw2, nullptr, out);
    // routed down: out += pair_w * (g_Ab seg @ w2e)
    k_g<2,1,64,NI,NH,3,2><<<dim3(NH/128, NE, 8), 256, SM_DN>>>(w2, nullptr, out);
}